// round 12
// baseline (speedup 1.0000x reference)
#include <cuda_runtime.h>
#include <math.h>

// Problem constants (static shapes from reference)
#define NN   2048      // nodes
#define NE   8192      // edges (E)
#define KK   1024      // K_KEEP
#define MNE  16384     // node-graph edges
#define MEE  65536     // edge-graph edges
#define CC   256       // feature dim (CN == CE)
#define LANM 48        // Lanczos iterations (R5 numerics, rel_err ~7e-5)

// Output layout (float offsets, concatenated flattened outputs in tuple order)
#define OFF_XN   0u         // x_n_out   [1024,256]
#define OFF_L0   262144u    // L0s       [1024,1024]
#define OFF_XE   1310720u   // x_e_out   [8192,256]
#define OFF_L1   3407872u   // L1s       [8192,8192]
#define OFF_PAR  70516736u  // par_masked[1024,8192]
#define OFF_XN0  78905344u  // x_n0_out  [1024,256]
#define OFF_XE0  79167488u  // x_e0_out  [8192,256]

// Flat zero space in float4: [0, 18874368) -> L1s+PAR contiguous, then L0.
#define ZB_SPLIT 18874368u
#define ZTOT     19136512u          // + 262144 (L0)
#define ZBLOCKS  4672               // ZTOT / 4096 f4 per block (64 KB/block)

// ---------------- scratch (device globals; re-initialized every launch) -----
__device__ float d_t_n[NN], d_u_n[NN], d_t_e[NE], d_u_e[NE];
__device__ float d_g_n[NN], d_g_e[NE];
__device__ float d_score_n[NN], d_score_e[NE], d_joint[NN];
__device__ int   d_mask[NN], d_idx_keep[KK];
__device__ float d_keep_f[NE];
__device__ int   d_kept_rs[NE], d_kept_rd[NE];
__device__ int   d_rowptr[KK + 1];
__device__ int   d_adj_node[2 * NE], d_adj_edge[2 * NE];
__device__ float d_adj_sign[2 * NE];
__device__ float d_scale;        // 2 / lambda_max(L0)

// ---- TWO non-default streams + events, created at static init --------------
// Chain must NOT run on the legacy NULL stream: NULL-stream launches carry
// implicit cross-stream sync edges, which serialized the R10/R11 "forks".
static cudaStream_t g_s1, g_s2;
static cudaEvent_t  g_evFork, g_evJoin1, g_evJoin2;
namespace {
struct HxStreamInit {
    HxStreamInit() {
        int lo = 0, hi = 0;
        cudaDeviceGetStreamPriorityRange(&lo, &hi);
        cudaStreamCreateWithPriority(&g_s1, cudaStreamNonBlocking, hi); // chain
        cudaStreamCreateWithPriority(&g_s2, cudaStreamNonBlocking, lo); // zero
        cudaEventCreateWithFlags(&g_evFork,  cudaEventDisableTiming);
        cudaEventCreateWithFlags(&g_evJoin1, cudaEventDisableTiming);
        cudaEventCreateWithFlags(&g_evJoin2, cudaEventDisableTiming);
    }
};
static HxStreamInit g_hxStreamInit;
}

// ---------------- KZ: bulk zero, SHORT blocks (64 KB each, then retire) -----
__global__ void __launch_bounds__(1024) k_zero(float* __restrict__ out) {
    float4* o4 = (float4*)out;
    const float4 z4 = make_float4(0.f, 0.f, 0.f, 0.f);
    unsigned base = blockIdx.x * 4096u + threadIdx.x;
#pragma unroll
    for (int k = 0; k < 4; k++) {
        unsigned idx = base + (unsigned)k * 1024u;
        unsigned a = (idx < ZB_SPLIT) ? (OFF_L1 / 4u + idx)
                                      : (OFF_L0 / 4u + (idx - ZB_SPLIT));
        o4[a] = z4;
    }
}

// ---------------- K1: per-row scalar projections + scratch zeroing ---------
__global__ void k_rows(const float* __restrict__ x_n, const float* __restrict__ x_e,
                       const float* __restrict__ Wn0, const float* __restrict__ Wn1,
                       const float* __restrict__ We0, const float* __restrict__ We1) {
    int gt = blockIdx.x * blockDim.x + threadIdx.x;
    if (gt < NN) { d_g_n[gt] = 0.f; d_joint[gt] = 0.f; }
    else if (gt < NN + NE) d_g_e[gt - NN] = 0.f;

    int row  = gt >> 5;
    int lane = gt & 31;
    if (row >= NN + NE) return;
    const float *x, *W0, *W1;
    if (row < NN) { x = x_n + (size_t)row * CC;        W0 = Wn0; W1 = Wn1; }
    else          { x = x_e + (size_t)(row - NN) * CC; W0 = We0; W1 = We1; }
    float u = 0.f, t = 0.f;
#pragma unroll
    for (int k = lane; k < CC; k += 32) {
        float xv = x[k];
        float w1 = W1[k];
        t = fmaf(xv, w1, t);
        u = fmaf(xv, W0[k] + w1, u);
    }
#pragma unroll
    for (int o = 16; o; o >>= 1) {
        u += __shfl_down_sync(0xffffffffu, u, o);
        t += __shfl_down_sync(0xffffffffu, t, o);
    }
    if (lane == 0) {
        if (row < NN) { d_u_n[row] = u; d_t_n[row] = t; }
        else          { d_u_e[row - NN] = u; d_t_e[row - NN] = t; }
    }
}

// ---------------- K2: scatter weighted scalar aggregates -------------------
__global__ void k_scatter_g(const int* __restrict__ ein, const float* __restrict__ ewn,
                            const int* __restrict__ eie, const float* __restrict__ ewe) {
    int i = blockIdx.x * blockDim.x + threadIdx.x;
    if (i < MNE) {
        int s = ein[i], d = ein[MNE + i];
        atomicAdd(&d_g_n[d], ewn[i] * d_t_n[s]);
    } else if (i < MNE + MEE) {
        int j = i - MNE;
        int s = eie[j], d = eie[MEE + j];
        atomicAdd(&d_g_e[d], ewe[j] * d_t_e[s]);
    }
}

// ---------------- K3: sigmoid scores + joint accumulation (fused) -----------
__global__ void k_scores_joint(const float* __restrict__ bn, const float* __restrict__ be,
                               const int* __restrict__ ei) {
    int i = blockIdx.x * blockDim.x + threadIdx.x;
    if (i < NN) {
        float z = d_u_n[i] - d_g_n[i] + bn[0];
        float s = 1.f / (1.f + expf(-z));
        d_score_n[i] = s;
        atomicAdd(&d_joint[i], s);
    } else if (i < NN + NE) {
        int j = i - NN;
        float z = d_u_e[j] - d_g_e[j] + be[0];
        float s = 1.f / (1.f + expf(-z));
        d_score_e[j] = s;
        float c = 0.125f * s;
        atomicAdd(&d_joint[ei[j]], c);
        atomicAdd(&d_joint[ei[NE + j]], c);
    }
}

// ---------------- K4: exact top-K by rank counting, one warp per node -------
__global__ void k_rank() {
    int gt = blockIdx.x * blockDim.x + threadIdx.x;
    int w = gt >> 5, lane = gt & 31;
    if (w >= NN) return;
    float vi = d_joint[w];
    int cnt = 0;
    for (int j = lane; j < NN; j += 32) {
        float vj = d_joint[j];
        cnt += (vj > vi) || (vj == vi && j < w);
    }
#pragma unroll
    for (int o = 16; o; o >>= 1) cnt += __shfl_down_sync(0xffffffffu, cnt, o);
    if (lane == 0) d_mask[w] = (cnt < KK) ? 1 : 0;
}

// ---------------- block exclusive scan helper (1024 threads) ----------------
__device__ __forceinline__ int exclScan1024(int v, int* tmp) {
    int lane = threadIdx.x & 31, w = threadIdx.x >> 5;
    int incl = v;
#pragma unroll
    for (int o = 1; o < 32; o <<= 1) {
        int n = __shfl_up_sync(0xffffffffu, incl, o);
        if (lane >= o) incl += n;
    }
    if (lane == 31) tmp[w] = incl;
    __syncthreads();
    if (w == 0) {
        int x = tmp[lane];
#pragma unroll
        for (int o = 1; o < 32; o <<= 1) {
            int n = __shfl_up_sync(0xffffffffu, x, o);
            if (lane >= o) x += n;
        }
        tmp[lane] = x;
    }
    __syncthreads();
    int off = w ? tmp[w - 1] : 0;
    return off + incl - v;
}

// ---------------- K5: single-block topology: compact + keep_e + CSR ---------
__global__ void __launch_bounds__(1024) k_topo(const int* __restrict__ ei) {
    __shared__ int s_row[NN];
    __shared__ int s_deg[KK];
    __shared__ int s_cur[KK];
    __shared__ int tmp[32];
    int tid = threadIdx.x;

    int m0 = d_mask[2 * tid], m1 = d_mask[2 * tid + 1];
    int ex = exclScan1024(m0 + m1, tmp);
    if (m0) { s_row[2 * tid] = ex; d_idx_keep[ex] = 2 * tid; }
    else    s_row[2 * tid] = -1;
    int ex1 = ex + m0;
    if (m1) { s_row[2 * tid + 1] = ex1; d_idx_keep[ex1] = 2 * tid + 1; }
    else    s_row[2 * tid + 1] = -1;
    s_deg[tid] = 0;
    s_cur[tid] = 0;
    __syncthreads();

    for (int e = tid; e < NE; e += 1024) {
        int s = ei[e], d = ei[NE + e];
        int rs = s_row[s], rd = s_row[d];
        int keep = (rs >= 0) && (rd >= 0);
        d_keep_f[e] = keep ? 1.f : 0.f;
        if (keep && s != d) {
            d_kept_rs[e] = rs;
            d_kept_rd[e] = rd;
            atomicAdd(&s_deg[rs], 1);
            atomicAdd(&s_deg[rd], 1);
        } else {
            d_kept_rs[e] = -1;
        }
    }
    __syncthreads();

    int v = s_deg[tid];
    int rp = exclScan1024(v, tmp);
    d_rowptr[tid] = rp;
    if (tid == 1023) d_rowptr[1024] = rp + v;
    __syncthreads();

    for (int e = tid; e < NE; e += 1024) {
        int rs = d_kept_rs[e];
        if (rs < 0) continue;
        int rd = d_kept_rd[e];
        int p = d_rowptr[rs] + atomicAdd(&s_cur[rs], 1);
        d_adj_node[p] = rd; d_adj_edge[p] = e; d_adj_sign[p] = -1.f;
        p = d_rowptr[rd] + atomicAdd(&s_cur[rd], 1);
        d_adj_node[p] = rs; d_adj_edge[p] = e; d_adj_sign[p] = 1.f;
    }
}

// ---------------- fused block reduction of two floats (1024 threads) ---------
__device__ __forceinline__ float2 blockReduce2(float a, float b, float2* red) {
    __syncthreads();
#pragma unroll
    for (int o = 16; o; o >>= 1) {
        a += __shfl_down_sync(0xffffffffu, a, o);
        b += __shfl_down_sync(0xffffffffu, b, o);
    }
    int lane = threadIdx.x & 31, w = threadIdx.x >> 5;
    if (lane == 0) red[w] = make_float2(a, b);
    __syncthreads();
    if (w == 0) {
        float2 x = red[lane];
#pragma unroll
        for (int o = 16; o; o >>= 1) {
            x.x += __shfl_down_sync(0xffffffffu, x.x, o);
            x.y += __shfl_down_sync(0xffffffffu, x.y, o);
        }
        if (lane == 0) red[0] = x;
    }
    __syncthreads();
    return red[0];
}

// ---------------- K6: feat: block0 = Lanczos, blocks 1..128 = features ------
__global__ void __launch_bounds__(1024) k_feat(
    float* __restrict__ out,
    const float* __restrict__ x_n,  const float* __restrict__ x_e,
    const float* __restrict__ x_n0, const float* __restrict__ x_e0)
{
    int tid = threadIdx.x;
    if (blockIdx.x == 0) {
        __shared__ float sv[KK];
        __shared__ float2 red[32];
        __shared__ float salpha[LANM], sbeta[LANM];
        __shared__ int   smeff;
        int r = tid;
        int p0 = d_rowptr[r], p1 = d_rowptr[r + 1];
        float degf = (float)(p1 - p0);
        unsigned h = (unsigned)r * 2654435761u + 0x9e3779b9u;
        h ^= h >> 16; h *= 0x85ebca6bu; h ^= h >> 13;
        float vr = ((float)(h & 0xFFFFFFu) / 16777216.0f) - 0.5f;
        float2 nn0 = blockReduce2(vr * vr, 0.f, red);
        vr = vr * rsqrtf(nn0.x);
        sv[r] = vr;
        if (r == 0) smeff = LANM;
        float vprev = 0.f, beta = 0.f;
        __syncthreads();
        for (int j = 0; j < LANM; j++) {
            float vcur = sv[r];
            float w = degf * vcur;
            for (int k = p0; k < p1; k++) w -= sv[d_adj_node[k]];
            w -= beta * vprev;
            float2 ab = blockReduce2(w * vcur, w * w, red);
            float alpha = ab.x;
            float b2 = ab.y - alpha * alpha;
            float nb = (b2 > 0.f) ? sqrtf(b2) : 0.f;
            if (r == 0) { salpha[j] = alpha; sbeta[j] = nb; }
            if (nb < 1e-10f) { if (r == 0) smeff = j + 1; break; }
            vprev = vcur;
            sv[r] = (w - alpha * vcur) / nb;
            beta = nb;
            __syncthreads();
        }
        __syncthreads();
        int meff = smeff;
        if (r < 32) {
            float lo = 1e30f, hi = -1e30f;
            for (int i = 0; i < meff; i++) {
                float a  = salpha[i];
                float bl = (i > 0) ? fabsf(sbeta[i - 1]) : 0.f;
                float br = (i < meff - 1) ? fabsf(sbeta[i]) : 0.f;
                lo = fminf(lo, a - bl - br);
                hi = fmaxf(hi, a + bl + br);
            }
            if (!(hi > lo)) hi = lo + 1.f;
            for (int round = 0; round < 10; round++) {
                float x = lo + (hi - lo) * ((float)(r + 1) / 33.0f);
                int cnt = 0; float dd = 1.f;
                for (int i = 0; i < meff; i++) {
                    float bb = (i > 0) ? sbeta[i - 1] * sbeta[i - 1] : 0.f;
                    dd = salpha[i] - x - bb / dd;
                    if (dd < 0.f) cnt++;
                    if (dd == 0.f) dd = -1e-20f;
                }
                bool allbelow = (cnt >= meff);
                unsigned mhi = __ballot_sync(0xffffffffu, allbelow);
                float nlo = lo, nhi = hi;
                if (mhi) {
                    int first = __ffs(mhi) - 1;
                    nhi = lo + (hi - lo) * ((float)(first + 1) / 33.0f);
                }
                unsigned mlo = ~mhi;
                if (mlo) {
                    int last = 31 - __clz(mlo);
                    nlo = lo + (hi - lo) * ((float)(last + 1) / 33.0f);
                }
                lo = nlo; hi = nhi;
            }
            if (r == 0) {
                float lam = 0.5f * (lo + hi);
                if (!(lam > 0.f)) lam = 1.f;
                d_scale = 2.0f / lam;
            }
        }
    } else {
        const float4* xn4  = (const float4*)x_n;
        const float4* xe4  = (const float4*)x_e;
        const float4* xn04 = (const float4*)x_n0;
        const float4* xe04 = (const float4*)x_e0;
        float4* o4 = (float4*)out;
        unsigned stride = (gridDim.x - 1) * 1024u;
        unsigned t0 = (blockIdx.x - 1) * 1024u + tid;
        for (unsigned i = t0; i < 65536u; i += stride) {      // kept-node feats
            unsigned rr = i >> 6, c = i & 63;
            int n = d_idx_keep[rr];
            float s = d_score_n[n];
            float4 a = xn4[(size_t)n * 64 + c];
            a.x *= s; a.y *= s; a.z *= s; a.w *= s;
            o4[OFF_XN / 4 + i]  = a;
            o4[OFF_XN0 / 4 + i] = xn04[(size_t)n * 64 + c];
        }
        for (unsigned i = t0; i < 524288u; i += stride) {     // edge feats
            unsigned e = i >> 6, c = i & 63;
            float kf = d_keep_f[e];
            float s = d_score_e[e] * kf;
            float4 a = xe4[(size_t)e * 64 + c];
            a.x *= s; a.y *= s; a.z *= s; a.w *= s;
            o4[OFF_XE / 4 + i] = a;
            float4 b0 = xe04[(size_t)e * 64 + c];
            b0.x *= kf; b0.y *= kf; b0.z *= kf; b0.w *= kf;
            o4[OFF_XE0 / 4 + i] = b0;
        }
    }
}

// ---------------- K7: scaled sparse fills -------------------------------------
__global__ void __launch_bounds__(1024) k_sparse(float* __restrict__ out) {
    float s = d_scale;
    int bid = blockIdx.x, tid = threadIdx.x;
    if (bid < 128) {
        int gw = bid * 32 + (tid >> 5);       // 4096 warps
        int r = gw >> 2;                      // kept-node row
        int q = gw & 3;                       // quarter
        int lane = tid & 31;
        int p0 = d_rowptr[r], p1 = d_rowptr[r + 1];
        int deg = p1 - p0;
        if (q == 0 && lane == 0)
            out[OFF_L0 + (size_t)r * KK + r] = (float)deg * s;
        float* L1 = out + OFF_L1;
        int tot = deg * deg;
        for (int p = (q << 5) + lane; p < tot; p += 128) {
            int i = p0 + p / deg;
            int j = p0 + p % deg;
            atomicAdd(&L1[(size_t)d_adj_edge[i] * NE + d_adj_edge[j]],
                      s * d_adj_sign[i] * d_adj_sign[j]);
        }
    } else {
        int e = (bid - 128) * 1024 + tid;
        if (e < NE) {
            int rs = d_kept_rs[e];
            if (rs >= 0) {
                int rd = d_kept_rd[e];
                out[OFF_PAR + (size_t)rs * NE + e] = -1.f;
                out[OFF_PAR + (size_t)rd * NE + e] =  1.f;
                float* L0 = out + OFF_L0;
                atomicAdd(&L0[(size_t)rs * KK + rd], -s);
                atomicAdd(&L0[(size_t)rd * KK + rs], -s);
            }
        }
    }
}

// ---------------- launch ------------------------------------------------------
extern "C" void kernel_launch(void* const* d_in, const int* in_sizes, int n_in,
                              void* d_out, int out_size) {
    const float* x_n  = (const float*)d_in[0];
    const int*   ein  = (const int*)d_in[1];
    const float* ewn  = (const float*)d_in[2];
    const float* x_e  = (const float*)d_in[3];
    const int*   eie  = (const int*)d_in[4];
    const float* ewe  = (const float*)d_in[5];
    const int*   ei   = (const int*)d_in[6];
    const float* x_n0 = (const float*)d_in[9];
    const float* x_e0 = (const float*)d_in[10];
    const float* Wn0  = (const float*)d_in[11];
    const float* Wn1  = (const float*)d_in[12];
    const float* bn   = (const float*)d_in[13];
    const float* We0  = (const float*)d_in[14];
    const float* We1  = (const float*)d_in[15];
    const float* be   = (const float*)d_in[16];
    float* out = (float*)d_out;

    // ---- fork from the capture stream onto TWO non-default streams ----
    cudaEventRecord(g_evFork, 0);
    cudaStreamWaitEvent(g_s2, g_evFork, 0);
    cudaStreamWaitEvent(g_s1, g_evFork, 0);

    // branch Z (low priority): bulk zero, short retire-fast blocks
    k_zero<<<ZBLOCKS, 1024, 0, g_s2>>>(out);
    cudaEventRecord(g_evJoin2, g_s2);

    // branch C (high priority): full scoring chain, NOT on the NULL stream
    k_rows<<<1280, 256, 0, g_s1>>>(x_n, x_e, Wn0, Wn1, We0, We1);
    k_scatter_g<<<(MNE + MEE + 255) / 256, 256, 0, g_s1>>>(ein, ewn, eie, ewe);
    k_scores_joint<<<(NN + NE + 255) / 256, 256, 0, g_s1>>>(bn, be, ei);
    k_rank<<<256, 256, 0, g_s1>>>();
    k_topo<<<1, 1024, 0, g_s1>>>(ei);
    k_feat<<<129, 1024, 0, g_s1>>>(out, x_n, x_e, x_n0, x_e0);
    cudaEventRecord(g_evJoin1, g_s1);

    // ---- join both branches into the capture stream; then sparse fills ----
    cudaStreamWaitEvent(0, g_evJoin1, 0);
    cudaStreamWaitEvent(0, g_evJoin2, 0);
    k_sparse<<<136, 1024>>>(out);
}

// round 13
// speedup vs baseline: 1.1558x; 1.1558x over previous
#include <cuda_runtime.h>
#include <math.h>

// Problem constants (static shapes from reference)
#define NN   2048      // nodes
#define NE   8192      // edges (E)
#define KK   1024      // K_KEEP
#define MNE  16384     // node-graph edges
#define MEE  65536     // edge-graph edges
#define CC   256       // feature dim (CN == CE)
#define LANM 48        // Lanczos iterations

// Output layout (float offsets, concatenated flattened outputs in tuple order)
#define OFF_XN   0u         // x_n_out   [1024,256]
#define OFF_L0   262144u    // L0s       [1024,1024]
#define OFF_XE   1310720u   // x_e_out   [8192,256]
#define OFF_L1   3407872u   // L1s       [8192,8192]
#define OFF_PAR  70516736u  // par_masked[1024,8192]
#define OFF_XN0  78905344u  // x_n0_out  [1024,256]
#define OFF_XE0  79167488u  // x_e0_out  [8192,256]

// ---------------- scratch (device globals; re-initialized every launch) ----
__device__ float d_t_n[NN], d_u_n[NN], d_t_e[NE], d_u_e[NE];
__device__ float d_g_n[NN], d_g_e[NE];
__device__ float d_score_n[NN], d_score_e[NE], d_joint[NN];
__device__ int   d_mask[NN], d_idx_keep[KK];
__device__ float d_keep_f[NE];
__device__ int   d_kept_rs[NE], d_kept_rd[NE];
__device__ int   d_rowptr[KK + 1];
__device__ int   d_adj_node[2 * NE], d_adj_edge[2 * NE];
__device__ float d_adj_sign[2 * NE];
__device__ float d_scale;   // 2 / lambda_max(L0)

// ---------------- K1: per-row scalar projections + scratch zeroing ---------
__global__ void k_rows(const float* __restrict__ x_n, const float* __restrict__ x_e,
                       const float* __restrict__ Wn0, const float* __restrict__ Wn1,
                       const float* __restrict__ We0, const float* __restrict__ We1) {
    int gt = blockIdx.x * blockDim.x + threadIdx.x;
    // zero per-launch accumulators (graph replays reuse device globals)
    if (gt < NN) { d_g_n[gt] = 0.f; d_joint[gt] = 0.f; }
    else if (gt < NN + NE) d_g_e[gt - NN] = 0.f;

    int row  = gt >> 5;
    int lane = gt & 31;
    if (row >= NN + NE) return;
    const float *x, *W0, *W1;
    if (row < NN) { x = x_n + (size_t)row * CC;        W0 = Wn0; W1 = Wn1; }
    else          { x = x_e + (size_t)(row - NN) * CC; W0 = We0; W1 = We1; }
    float u = 0.f, t = 0.f;
#pragma unroll
    for (int k = lane; k < CC; k += 32) {
        float xv = x[k];
        float w1 = W1[k];
        t = fmaf(xv, w1, t);
        u = fmaf(xv, W0[k] + w1, u);
    }
#pragma unroll
    for (int o = 16; o; o >>= 1) {
        u += __shfl_down_sync(0xffffffffu, u, o);
        t += __shfl_down_sync(0xffffffffu, t, o);
    }
    if (lane == 0) {
        if (row < NN) { d_u_n[row] = u; d_t_n[row] = t; }
        else          { d_u_e[row - NN] = u; d_t_e[row - NN] = t; }
    }
}

// ---------------- K2: scatter weighted scalar aggregates -------------------
__global__ void k_scatter_g(const int* __restrict__ ein, const float* __restrict__ ewn,
                            const int* __restrict__ eie, const float* __restrict__ ewe) {
    int i = blockIdx.x * blockDim.x + threadIdx.x;
    if (i < MNE) {
        int s = ein[i], d = ein[MNE + i];
        atomicAdd(&d_g_n[d], ewn[i] * d_t_n[s]);
    } else if (i < MNE + MEE) {
        int j = i - MNE;
        int s = eie[j], d = eie[MEE + j];
        atomicAdd(&d_g_e[d], ewe[j] * d_t_e[s]);
    }
}

// ---------------- K3: sigmoid scores + joint accumulation (fused) -----------
__global__ void k_scores_joint(const float* __restrict__ bn, const float* __restrict__ be,
                               const int* __restrict__ ei) {
    int i = blockIdx.x * blockDim.x + threadIdx.x;
    if (i < NN) {
        float z = d_u_n[i] - d_g_n[i] + bn[0];
        float s = 1.f / (1.f + expf(-z));
        d_score_n[i] = s;
        atomicAdd(&d_joint[i], s);
    } else if (i < NN + NE) {
        int j = i - NN;
        float z = d_u_e[j] - d_g_e[j] + be[0];
        float s = 1.f / (1.f + expf(-z));
        d_score_e[j] = s;
        float c = 0.125f * s;
        atomicAdd(&d_joint[ei[j]], c);
        atomicAdd(&d_joint[ei[NE + j]], c);
    }
}

// ---------------- K4: exact top-K by rank counting, one warp per node -------
__global__ void k_rank() {
    int gt = blockIdx.x * blockDim.x + threadIdx.x;
    int w = gt >> 5, lane = gt & 31;
    if (w >= NN) return;
    float vi = d_joint[w];
    int cnt = 0;
    for (int j = lane; j < NN; j += 32) {
        float vj = d_joint[j];
        cnt += (vj > vi) || (vj == vi && j < w);
    }
#pragma unroll
    for (int o = 16; o; o >>= 1) cnt += __shfl_down_sync(0xffffffffu, cnt, o);
    if (lane == 0) d_mask[w] = (cnt < KK) ? 1 : 0;
}

// ---------------- block exclusive scan helper (1024 threads) ----------------
__device__ __forceinline__ int exclScan1024(int v, int* tmp) {
    int lane = threadIdx.x & 31, w = threadIdx.x >> 5;
    int incl = v;
#pragma unroll
    for (int o = 1; o < 32; o <<= 1) {
        int n = __shfl_up_sync(0xffffffffu, incl, o);
        if (lane >= o) incl += n;
    }
    if (lane == 31) tmp[w] = incl;
    __syncthreads();
    if (w == 0) {
        int x = tmp[lane];
#pragma unroll
        for (int o = 1; o < 32; o <<= 1) {
            int n = __shfl_up_sync(0xffffffffu, x, o);
            if (lane >= o) x += n;
        }
        tmp[lane] = x;
    }
    __syncthreads();
    int off = w ? tmp[w - 1] : 0;
    return off + incl - v;
}

// ---------------- K5: single-block topology: compact + keep_e + CSR ---------
__global__ void __launch_bounds__(1024) k_topo(const int* __restrict__ ei) {
    __shared__ int s_row[NN];     // row_of (or -1)
    __shared__ int s_deg[KK];
    __shared__ int s_cur[KK];
    __shared__ int tmp[32];
    int tid = threadIdx.x;

    // Phase A: compact kept nodes -> idx_keep (ascending), row map
    int m0 = d_mask[2 * tid], m1 = d_mask[2 * tid + 1];
    int ex = exclScan1024(m0 + m1, tmp);
    if (m0) { s_row[2 * tid] = ex; d_idx_keep[ex] = 2 * tid; }
    else    s_row[2 * tid] = -1;
    int ex1 = ex + m0;
    if (m1) { s_row[2 * tid + 1] = ex1; d_idx_keep[ex1] = 2 * tid + 1; }
    else    s_row[2 * tid + 1] = -1;
    s_deg[tid] = 0;
    s_cur[tid] = 0;
    __syncthreads();

    // Phase B: keep_e + endpoint rows + degree count
    for (int e = tid; e < NE; e += 1024) {
        int s = ei[e], d = ei[NE + e];
        int rs = s_row[s], rd = s_row[d];
        int keep = (rs >= 0) && (rd >= 0);
        d_keep_f[e] = keep ? 1.f : 0.f;
        if (keep && s != d) {
            d_kept_rs[e] = rs;
            d_kept_rd[e] = rd;
            atomicAdd(&s_deg[rs], 1);
            atomicAdd(&s_deg[rd], 1);
        } else {
            d_kept_rs[e] = -1;
        }
    }
    __syncthreads();

    // Phase C: row pointers (exclusive scan of degrees)
    int v = s_deg[tid];
    int rp = exclScan1024(v, tmp);
    d_rowptr[tid] = rp;
    if (tid == 1023) d_rowptr[1024] = rp + v;
    __syncthreads();

    // Phase D: CSR fill
    for (int e = tid; e < NE; e += 1024) {
        int rs = d_kept_rs[e];
        if (rs < 0) continue;
        int rd = d_kept_rd[e];
        int p = d_rowptr[rs] + atomicAdd(&s_cur[rs], 1);
        d_adj_node[p] = rd; d_adj_edge[p] = e; d_adj_sign[p] = -1.f;
        p = d_rowptr[rd] + atomicAdd(&s_cur[rd], 1);
        d_adj_node[p] = rs; d_adj_edge[p] = e; d_adj_sign[p] = 1.f;
    }
}

// ---------------- fused block reduction of two floats (1024 threads) ---------
__device__ __forceinline__ float2 blockReduce2(float a, float b, float2* red) {
    __syncthreads();  // protect shared scratch reuse across calls
#pragma unroll
    for (int o = 16; o; o >>= 1) {
        a += __shfl_down_sync(0xffffffffu, a, o);
        b += __shfl_down_sync(0xffffffffu, b, o);
    }
    int lane = threadIdx.x & 31, w = threadIdx.x >> 5;
    if (lane == 0) red[w] = make_float2(a, b);
    __syncthreads();
    if (w == 0) {
        float2 x = red[lane];
#pragma unroll
        for (int o = 16; o; o >>= 1) {
            x.x += __shfl_down_sync(0xffffffffu, x.x, o);
            x.y += __shfl_down_sync(0xffffffffu, x.y, o);
        }
        if (lane == 0) red[0] = x;
    }
    __syncthreads();
    return red[0];
}

// ---------------- K6: mega-kernel: block0 = Lanczos, others = zero+copy -----
__global__ void __launch_bounds__(1024) k_mega(
    float* __restrict__ out,
    const float* __restrict__ x_n,  const float* __restrict__ x_e,
    const float* __restrict__ x_n0, const float* __restrict__ x_e0)
{
    if (blockIdx.x == 0) {
        // ---- Lanczos on L0 (kept-subgraph Laplacian), n = 1024 ----
        __shared__ float sv[KK];
        __shared__ float2 red[32];
        __shared__ float salpha[LANM], sbeta[LANM];
        __shared__ int   smeff;
        int r = threadIdx.x;
        int p0 = d_rowptr[r], p1 = d_rowptr[r + 1];
        float degf = (float)(p1 - p0);

        // deterministic pseudo-random start vector (not constant: ones = null vec)
        unsigned h = (unsigned)r * 2654435761u + 0x9e3779b9u;
        h ^= h >> 16; h *= 0x85ebca6bu; h ^= h >> 13;
        float vr = ((float)(h & 0xFFFFFFu) / 16777216.0f) - 0.5f;
        float2 nn0 = blockReduce2(vr * vr, 0.f, red);
        vr = vr * rsqrtf(nn0.x);
        sv[r] = vr;
        if (r == 0) smeff = LANM;
        float vprev = 0.f, beta = 0.f;
        __syncthreads();

        for (int j = 0; j < LANM; j++) {
            float vcur = sv[r];
            float w = degf * vcur;
            for (int k = p0; k < p1; k++) w -= sv[d_adj_node[k]];
            w -= beta * vprev;
            // fused: alpha = w.v ; s2 = w.w ; beta^2 = s2 - alpha^2
            float2 ab = blockReduce2(w * vcur, w * w, red);
            float alpha = ab.x;
            float b2 = ab.y - alpha * alpha;
            float nb = (b2 > 0.f) ? sqrtf(b2) : 0.f;
            if (r == 0) { salpha[j] = alpha; sbeta[j] = nb; }
            if (nb < 1e-10f) { if (r == 0) smeff = j + 1; break; }   // uniform exit
            vprev = vcur;
            // blockReduce2 already synced: all gathers of old sv are done
            sv[r] = (w - alpha * vcur) / nb;
            beta = nb;
            __syncthreads();
        }
        __syncthreads();
        int meff = smeff;

        // ---- warp-parallel 32-way multisection Sturm bisection on T ----
        if (r < 32) {
            float lo = 1e30f, hi = -1e30f;
            for (int i = 0; i < meff; i++) {
                float a  = salpha[i];
                float bl = (i > 0) ? fabsf(sbeta[i - 1]) : 0.f;
                float br = (i < meff - 1) ? fabsf(sbeta[i]) : 0.f;
                lo = fminf(lo, a - bl - br);
                hi = fmaxf(hi, a + bl + br);
            }
            if (!(hi > lo)) hi = lo + 1.f;
            for (int round = 0; round < 10; round++) {
                float x = lo + (hi - lo) * ((float)(r + 1) / 33.0f);
                int cnt = 0; float dd = 1.f;
                for (int i = 0; i < meff; i++) {
                    float bb = (i > 0) ? sbeta[i - 1] * sbeta[i - 1] : 0.f;
                    dd = salpha[i] - x - bb / dd;
                    if (dd < 0.f) cnt++;
                    if (dd == 0.f) dd = -1e-20f;
                }
                bool allbelow = (cnt >= meff);
                unsigned mhi = __ballot_sync(0xffffffffu, allbelow);
                float nlo = lo, nhi = hi;
                if (mhi) {
                    int first = __ffs(mhi) - 1;
                    nhi = lo + (hi - lo) * ((float)(first + 1) / 33.0f);
                }
                unsigned mlo = ~mhi;
                if (mlo) {
                    int last = 31 - __clz(mlo);
                    nlo = lo + (hi - lo) * ((float)(last + 1) / 33.0f);
                }
                lo = nlo; hi = nhi;
            }
            if (r == 0) {
                float lam = 0.5f * (lo + hi);
                if (!(lam > 0.f)) lam = 1.f;   // degenerate-graph guard
                d_scale = 2.0f / lam;
            }
        }
    } else {
        // ---- zero sparse output regions + write feature outputs ----
        const float4* xn4  = (const float4*)x_n;
        const float4* xe4  = (const float4*)x_e;
        const float4* xn04 = (const float4*)x_n0;
        const float4* xe04 = (const float4*)x_e0;
        float4* o4 = (float4*)out;
        unsigned stride = (gridDim.x - 1) * 1024u;
        unsigned t0 = (blockIdx.x - 1) * 1024u + threadIdx.x;
        float4 z4 = make_float4(0.f, 0.f, 0.f, 0.f);
        for (unsigned i = t0; i < 262144u;   i += stride) o4[OFF_L0 / 4 + i]  = z4;
        for (unsigned i = t0; i < 16777216u; i += stride) o4[OFF_L1 / 4 + i]  = z4;
        for (unsigned i = t0; i < 2097152u;  i += stride) o4[OFF_PAR / 4 + i] = z4;
        for (unsigned i = t0; i < 65536u; i += stride) {          // kept-node features
            unsigned rr = i >> 6, c = i & 63;
            int n = d_idx_keep[rr];
            float s = d_score_n[n];
            float4 a = xn4[(size_t)n * 64 + c];
            a.x *= s; a.y *= s; a.z *= s; a.w *= s;
            o4[OFF_XN / 4 + i]  = a;
            o4[OFF_XN0 / 4 + i] = xn04[(size_t)n * 64 + c];
        }
        for (unsigned i = t0; i < 524288u; i += stride) {         // edge features
            unsigned e = i >> 6, c = i & 63;
            float kf = d_keep_f[e];
            float s = d_score_e[e] * kf;
            float4 a = xe4[(size_t)e * 64 + c];
            a.x *= s; a.y *= s; a.z *= s; a.w *= s;
            o4[OFF_XE / 4 + i] = a;
            float4 b0 = xe04[(size_t)e * 64 + c];
            b0.x *= kf; b0.y *= kf; b0.z *= kf; b0.w *= kf;
            o4[OFF_XE0 / 4 + i] = b0;
        }
    }
}

// ---------------- K7: scaled sparse fills (4 warps per kept-node row) -------
// Blocks 0..127: L1s pair-scatter — four warps cover each row's deg^2 pair
// space (latency fix for the measured 6.1us 1-warp version); direct L0 diag.
// Blocks 128..135: PAR stores + L0 off-diagonal atomics per kept edge.
__global__ void __launch_bounds__(1024) k_sparse(float* __restrict__ out) {
    float s = d_scale;
    int bid = blockIdx.x, tid = threadIdx.x;
    if (bid < 128) {
        int gw = bid * 32 + (tid >> 5);       // 4096 warps
        int r = gw >> 2;                      // kept-node row, 0..1023
        int q = gw & 3;                       // quarter
        int lane = tid & 31;
        int p0 = d_rowptr[r], p1 = d_rowptr[r + 1];
        int deg = p1 - p0;
        if (q == 0 && lane == 0)              // L0 diagonal, direct store
            out[OFF_L0 + (size_t)r * KK + r] = (float)deg * s;
        float* L1 = out + OFF_L1;
        int tot = deg * deg;
        for (int p = (q << 5) + lane; p < tot; p += 128) {
            int i = p0 + p / deg;
            int j = p0 + p % deg;
            atomicAdd(&L1[(size_t)d_adj_edge[i] * NE + d_adj_edge[j]],
                      s * d_adj_sign[i] * d_adj_sign[j]);
        }
    } else {
        int e = (bid - 128) * 1024 + tid;
        if (e < NE) {
            int rs = d_kept_rs[e];
            if (rs >= 0) {
                int rd = d_kept_rd[e];
                out[OFF_PAR + (size_t)rs * NE + e] = -1.f;
                out[OFF_PAR + (size_t)rd * NE + e] =  1.f;
                float* L0 = out + OFF_L0;
                atomicAdd(&L0[(size_t)rs * KK + rd], -s);
                atomicAdd(&L0[(size_t)rd * KK + rs], -s);
            }
        }
    }
}

// ---------------- launch ------------------------------------------------------
extern "C" void kernel_launch(void* const* d_in, const int* in_sizes, int n_in,
                              void* d_out, int out_size) {
    const float* x_n  = (const float*)d_in[0];
    const int*   ein  = (const int*)d_in[1];
    const float* ewn  = (const float*)d_in[2];
    const float* x_e  = (const float*)d_in[3];
    const int*   eie  = (const int*)d_in[4];
    const float* ewe  = (const float*)d_in[5];
    const int*   ei   = (const int*)d_in[6];
    // d_in[7] n_batch, d_in[8] e_batch: unused (single graph)
    const float* x_n0 = (const float*)d_in[9];
    const float* x_e0 = (const float*)d_in[10];
    const float* Wn0  = (const float*)d_in[11];
    const float* Wn1  = (const float*)d_in[12];
    const float* bn   = (const float*)d_in[13];
    const float* We0  = (const float*)d_in[14];
    const float* We1  = (const float*)d_in[15];
    const float* be   = (const float*)d_in[16];
    float* out = (float*)d_out;

    k_rows<<<1280, 256>>>(x_n, x_e, Wn0, Wn1, We0, We1);
    k_scatter_g<<<(MNE + MEE + 255) / 256, 256>>>(ein, ewn, eie, ewe);
    k_scores_joint<<<(NN + NE + 255) / 256, 256>>>(bn, be, ei);
    k_rank<<<256, 256>>>();
    k_topo<<<1, 1024>>>(ei);
    k_mega<<<593, 1024>>>(out, x_n, x_e, x_n0, x_e0);
    k_sparse<<<136, 1024>>>(out);
}